// round 2
// baseline (speedup 1.0000x reference)
#include <cuda_runtime.h>
#include <cstdint>

#define BN 1024
#define DN 256
#define LN 32

// Scratch (no allocations allowed)
__device__ int g_count[LN];
__device__ int g_neglist[LN * BN];

// ---------------------------------------------------------------------------
// Kernel 1: label histogram (labels in [0, 32)), one block of BN threads.
// ---------------------------------------------------------------------------
__global__ void hist_kernel(const int* __restrict__ label) {
    __shared__ int h[LN];
    int t = threadIdx.x;
    if (t < LN) h[t] = 0;
    __syncthreads();
    atomicAdd(&h[label[t]], 1);
    __syncthreads();
    if (t < LN) g_count[t] = h[t];
}

// ---------------------------------------------------------------------------
// Kernel 2: for each label l, compact (in original order) all row indices k
// with label[k] != l into g_neglist[l*BN ...]. One block per label,
// BN threads, ballot/popc block-wide stable compaction.
// ---------------------------------------------------------------------------
__global__ void neglist_kernel(const int* __restrict__ label) {
    int l = blockIdx.x;
    int t = threadIdx.x;
    int lane = t & 31;
    int wid  = t >> 5;
    __shared__ int wsum[32];

    bool flag = (label[t] != l);
    unsigned m = __ballot_sync(0xffffffffu, flag);
    int rank = __popc(m & ((1u << lane) - 1u));
    if (lane == 0) wsum[wid] = __popc(m);
    __syncthreads();
    if (wid == 0) {
        int v = wsum[lane];
        int s = v;
        #pragma unroll
        for (int o = 1; o < 32; o <<= 1) {
            int n = __shfl_up_sync(0xffffffffu, s, o);
            if (lane >= o) s += n;
        }
        wsum[lane] = s - v;  // exclusive prefix of warp totals
    }
    __syncthreads();
    if (flag) g_neglist[l * BN + wsum[wid] + rank] = t;
}

// ---------------------------------------------------------------------------
// Threefry-2x32 (JAX partitionable scheme), key = (0, 42).
// 32-bit random word for flat counter t:  bits = out0 ^ out1 of
// threefry2x32(key, (hi(t)=0, lo(t)=t)).
// ---------------------------------------------------------------------------
__device__ __forceinline__ uint32_t rotl32(uint32_t x, int r) {
    return (x << r) | (x >> (32 - r));
}

__device__ __forceinline__ uint32_t threefry_bits32(uint32_t x0, uint32_t x1) {
    const uint32_t k0 = 0u, k1 = 42u;
    const uint32_t k2 = k0 ^ k1 ^ 0x1BD11BDAu;
    x0 += k0; x1 += k1;
#define TF_ROUND(r) { x0 += x1; x1 = rotl32(x1, (r)); x1 ^= x0; }
    TF_ROUND(13) TF_ROUND(15) TF_ROUND(26) TF_ROUND(6)
    x0 += k1; x1 += k2 + 1u;
    TF_ROUND(17) TF_ROUND(29) TF_ROUND(16) TF_ROUND(24)
    x0 += k2; x1 += k0 + 2u;
    TF_ROUND(13) TF_ROUND(15) TF_ROUND(26) TF_ROUND(6)
    x0 += k0; x1 += k1 + 3u;
    TF_ROUND(17) TF_ROUND(29) TF_ROUND(16) TF_ROUND(24)
    x0 += k1; x1 += k2 + 4u;
    TF_ROUND(13) TF_ROUND(15) TF_ROUND(26) TF_ROUND(6)
    x0 += k2; x1 += k0 + 5u;
#undef TF_ROUND
    return x0 ^ x1;   // partitionable 32-bit path XORs the two output words
}

// ---------------------------------------------------------------------------
// Kernel 3: gather. One warp per output row (i, j). Lane 0 resolves the
// source row index (threefry resample only on the padded tail), broadcast,
// then a fully-coalesced 1 KB row copy (2 x float4 per lane).
// ---------------------------------------------------------------------------
__global__ void gather_kernel(const float* __restrict__ embs,
                              const int* __restrict__ label,
                              float* __restrict__ out,
                              int max_count, int total) {
    int warp = blockIdx.x * (blockDim.x >> 5) + (threadIdx.x >> 5);
    if (warp >= total) return;
    int lane = threadIdx.x & 31;

    int idx = 0;
    if (lane == 0) {
        int i = warp / max_count;
        int j = warp - i * max_count;
        int l = label[i];
        int nc = BN - g_count[l];
        int p = j;
        if (j >= nc) {
            // u[t] with t = i*max_count + j = warp (row-major flat index)
            uint32_t bits = threefry_bits32(0u, (uint32_t)warp);
            float u = __uint_as_float((bits >> 9) | 0x3F800000u) - 1.0f;
            p = (int)__fmul_rn(u, (float)nc);   // trunc toward zero, matches XLA
            int cap = nc - 1;
            if (p > cap) p = cap;
        }
        idx = g_neglist[l * BN + p];
    }
    idx = __shfl_sync(0xffffffffu, idx, 0);

    const float4* src = (const float4*)embs + (size_t)idx  * (DN / 4);
    float4*       dst = (float4*)out        + (size_t)warp * (DN / 4);
    dst[lane]      = src[lane];
    dst[lane + 32] = src[lane + 32];
}

// ---------------------------------------------------------------------------
extern "C" void kernel_launch(void* const* d_in, const int* in_sizes, int n_in,
                              void* d_out, int out_size) {
    const float* embs  = (const float*)d_in[0];
    const int*   label = (const int*)d_in[1];
    // Defensive: metadata order should be (embs[BN*DN], label[BN]); swap if not.
    if (n_in >= 2 && in_sizes[0] == BN && in_sizes[1] == BN * DN) {
        embs  = (const float*)d_in[1];
        label = (const int*)d_in[0];
    }

    int max_count = out_size / (BN * DN);
    int total = BN * max_count;

    hist_kernel<<<1, BN>>>(label);
    neglist_kernel<<<LN, BN>>>(label);

    const int warps_per_block = 8;  // 256 threads
    int grid = (total + warps_per_block - 1) / warps_per_block;
    gather_kernel<<<grid, warps_per_block * 32>>>(
        embs, label, (float*)d_out, max_count, total);
}

// round 3
// speedup vs baseline: 1.0956x; 1.0956x over previous
#include <cuda_runtime.h>
#include <cstdint>

#define BN 1024
#define DN 256
#define LN 32

// Scratch (no allocations allowed)
__device__ int g_negcnt[LN];            // #rows with label != l
__device__ int g_neglist[LN * BN];      // stable-ordered negative row indices
__device__ int g_poscnt[LN];            // #anchors with label == l
__device__ int g_poslist[LN * BN];      // anchor row indices (order irrelevant)

// ---------------------------------------------------------------------------
// Kernel 1: per-label lists + counts. One block per label, 1024 threads.
// Stable block-wide compaction via ballot/popc + warp-sum scan.
// ---------------------------------------------------------------------------
__global__ void lists_kernel(const int* __restrict__ label) {
    int l = blockIdx.x;
    int t = threadIdx.x;
    int lane = t & 31;
    int wid  = t >> 5;
    __shared__ int wpre[32];   // exclusive prefix of per-warp NEG counts
    __shared__ int s_total;    // total NEG count

    bool neg = (label[t] != l);
    unsigned m = __ballot_sync(0xffffffffu, neg);
    int nrank = __popc(m & ((1u << lane) - 1u));   // neg rank within warp
    if (lane == 0) wpre[wid] = __popc(m);
    __syncthreads();
    if (wid == 0) {
        int v = wpre[lane];
        int s = v;
        #pragma unroll
        for (int o = 1; o < 32; o <<= 1) {
            int n = __shfl_up_sync(0xffffffffu, s, o);
            if (lane >= o) s += n;
        }
        if (lane == 31) s_total = s;   // inclusive total = block neg count
        wpre[lane] = s - v;            // exclusive prefix
    }
    __syncthreads();

    if (neg) {
        g_neglist[l * BN + wpre[wid] + nrank] = t;
    } else {
        // pos exclusive prefix = (threads before warp) - (neg before warp)
        int ppre  = (wid << 5) - wpre[wid];
        int prank = lane - nrank;      // pos rank within warp
        g_poslist[l * BN + ppre + prank] = t;
    }
    if (t == 0) {
        int nc = s_total;
        g_negcnt[l] = nc;
        g_poscnt[l] = BN - nc;
    }
}

// ---------------------------------------------------------------------------
// Threefry-2x32 (JAX partitionable scheme), key = (0, 42).
// bits(t) = out0 ^ out1 of threefry2x32(key, (hi=0, lo=t)).
// ---------------------------------------------------------------------------
__device__ __forceinline__ uint32_t rotl32(uint32_t x, int r) {
    return (x << r) | (x >> (32 - r));
}

__device__ __forceinline__ uint32_t threefry_bits32(uint32_t x0, uint32_t x1) {
    const uint32_t k0 = 0u, k1 = 42u;
    const uint32_t k2 = k0 ^ k1 ^ 0x1BD11BDAu;
    x0 += k0; x1 += k1;
#define TF_ROUND(r) { x0 += x1; x1 = rotl32(x1, (r)); x1 ^= x0; }
    TF_ROUND(13) TF_ROUND(15) TF_ROUND(26) TF_ROUND(6)
    x0 += k1; x1 += k2 + 1u;
    TF_ROUND(17) TF_ROUND(29) TF_ROUND(16) TF_ROUND(24)
    x0 += k2; x1 += k0 + 2u;
    TF_ROUND(13) TF_ROUND(15) TF_ROUND(26) TF_ROUND(6)
    x0 += k0; x1 += k1 + 3u;
    TF_ROUND(17) TF_ROUND(29) TF_ROUND(16) TF_ROUND(24)
    x0 += k1; x1 += k2 + 4u;
    TF_ROUND(13) TF_ROUND(15) TF_ROUND(26) TF_ROUND(6)
    x0 += k2; x1 += k0 + 5u;
#undef TF_ROUND
    return x0 ^ x1;
}

// ---------------------------------------------------------------------------
// Kernel 2: gather with source-row reuse.
// Block = (j = blockIdx.x, label l = blockIdx.y), 256 threads = 8 warps.
//   j <  nc_l : read embs[neglist_l[j]] ONCE into shared, broadcast-write it
//               to all count_l anchors of label l (identical for all of them).
//   j >= nc_l : padded tail — per-anchor threefry resample, direct gather.
// L2 read traffic drops ~32x vs one-read-per-row; DRAM writes unchanged.
// ---------------------------------------------------------------------------
__global__ void gather_kernel(const float* __restrict__ embs,
                              float* __restrict__ out,
                              int max_count) {
    int j = blockIdx.x;
    int l = blockIdx.y;
    int nc = g_negcnt[l];
    int pc = g_poscnt[l];
    if (pc == 0) return;

    int lane = threadIdx.x & 31;
    int w    = threadIdx.x >> 5;
    __shared__ float4 srow[DN / 4];   // 1 KB

    if (j < nc) {
        int src = g_neglist[l * BN + j];
        if (threadIdx.x < DN / 4)
            srow[threadIdx.x] = ((const float4*)embs)[(size_t)src * (DN / 4) + threadIdx.x];
        __syncthreads();
        float4 v0 = srow[lane];
        float4 v1 = srow[lane + 32];
        for (int a = w; a < pc; a += 8) {
            int i = g_poslist[l * BN + a];
            float4* dst = (float4*)out + ((size_t)i * max_count + j) * (DN / 4);
            dst[lane]      = v0;
            dst[lane + 32] = v1;
        }
    } else {
        // tail: per-anchor uniform resample among the nc negatives
        for (int a = w; a < pc; a += 8) {
            int i = g_poslist[l * BN + a];
            int p = 0;
            if (lane == 0) {
                uint32_t t = (uint32_t)(i * max_count + j);   // row-major flat idx
                uint32_t bits = threefry_bits32(0u, t);
                float u = __uint_as_float((bits >> 9) | 0x3F800000u) - 1.0f;
                p = (int)__fmul_rn(u, (float)nc);             // trunc, matches XLA
                int cap = nc - 1;
                if (p > cap) p = cap;
            }
            p = __shfl_sync(0xffffffffu, p, 0);
            int src = g_neglist[l * BN + p];
            const float4* s = (const float4*)embs + (size_t)src * (DN / 4);
            float4*     dst = (float4*)out + ((size_t)i * max_count + j) * (DN / 4);
            dst[lane]      = s[lane];
            dst[lane + 32] = s[lane + 32];
        }
    }
}

// ---------------------------------------------------------------------------
extern "C" void kernel_launch(void* const* d_in, const int* in_sizes, int n_in,
                              void* d_out, int out_size) {
    const float* embs  = (const float*)d_in[0];
    const int*   label = (const int*)d_in[1];
    // Defensive: metadata order should be (embs[BN*DN], label[BN]); swap if not.
    if (n_in >= 2 && in_sizes[0] == BN && in_sizes[1] == BN * DN) {
        embs  = (const float*)d_in[1];
        label = (const int*)d_in[0];
    }

    int max_count = out_size / (BN * DN);

    lists_kernel<<<LN, BN>>>(label);

    dim3 grid(max_count, LN);
    gather_kernel<<<grid, 256>>>(embs, (float*)d_out, max_count);
}